// round 3
// baseline (speedup 1.0000x reference)
#include <cuda_runtime.h>

// MSAAttentionBlock fused kernel (fp32 baseline).
// Per 32-voxel tile: X(smem) -> Q,K,V -> per-voxel head attention -> FFN -> residual+BN -> out.
// All intermediates live in shared memory; weights staged through a shared k-tile buffer.

#define THREADS 256
#define TILE_M  32
#define BK      16
#define BN_EPS  1e-6f

// shared memory layout (float offsets)
#define XS_OFF     0        // [32][256]  32KB  (resident: x tile)
#define Q_OFF      8192     // [32][512]  64KB
#define KB_OFF     24576    // [32][512]  64KB
#define VB_OFF     40960    // [32][256]  32KB  (v, then attn_out, then o2)
#define BS_OFF     49152    // [16][512]  32KB  (weight k-tile)
#define INTER_OFF  8192     // [32][1024] 128KB (overlaps Q+KB, used after attention)
#define SMEM_FLOATS 57344
#define SMEM_BYTES  (SMEM_FLOATS * 4)   // 229376 B <= 232448 B (227KB) sm_103a limit

struct FinalP {
    const float* gamma;
    const float* beta;
    const float* mu;
    const float* var;
    const float* o2;     // smem o2 [32][256]
    float*       out;    // global output
    int          voxBase;
};

// C[32][NC] (+ncOff) = A[32][K] @ W[K][ldw] slice, bias add, optional relu / final epilogue.
// EPI: 0 = store to smem, 1 = store+relu to smem, 2 = final (relu + o2 + batchnorm -> global)
template <int NC, int EPI>
__device__ __forceinline__ void gemm_tile(
    const float* A, int lda, int K,
    const float* __restrict__ W, int ldw, int ncOff,
    const float* __restrict__ bias,
    float* outS, int ldo, int outOff,
    float* Bs, const FinalP* fp)
{
    constexpr int NB = NC / 8;        // n-blocks (threads along n)
    constexpr int MG = THREADS / NB;  // m-groups
    constexpr int TM = TILE_M / MG;   // rows per thread
    const int tid  = threadIdx.x;
    const int nIdx = tid % NB;
    const int mIdx = tid / NB;
    const int m0   = mIdx * TM;
    const int cA   = nIdx * 4;        // split-column layout: conflict-free LDS.128
    const int cB   = cA + NC / 2;

    float acc[TM][8];
#pragma unroll
    for (int i = 0; i < TM; i++)
#pragma unroll
        for (int j = 0; j < 8; j++) acc[i][j] = 0.f;

    const int KT = K / BK;
    for (int kt = 0; kt < KT; ++kt) {
        __syncthreads();   // protect Bs (prev consumers done) + previous phase outputs
        {
            constexpr int ELEMS = BK * NC;
            const float* Wrow = W + (size_t)kt * BK * ldw + ncOff;
#pragma unroll
            for (int base = 0; base < ELEMS; base += THREADS * 4) {
                int idx = base + tid * 4;
                int r = idx / NC;
                int c = idx - r * NC;
                float4 v = *(const float4*)(Wrow + (size_t)r * ldw + c);
                *(float4*)(Bs + idx) = v;
            }
        }
        __syncthreads();

        const float* Ak = A + kt * BK;
#pragma unroll
        for (int kk4 = 0; kk4 < BK / 4; ++kk4) {
            float a[TM][4];
#pragma unroll
            for (int i = 0; i < TM; i++) {
                float4 t4 = *(const float4*)(Ak + (m0 + i) * lda + kk4 * 4);
                a[i][0] = t4.x; a[i][1] = t4.y; a[i][2] = t4.z; a[i][3] = t4.w;
            }
#pragma unroll
            for (int t = 0; t < 4; t++) {
                const float* Br = Bs + (kk4 * 4 + t) * NC;
                float4 b0 = *(const float4*)(Br + cA);
                float4 b1 = *(const float4*)(Br + cB);
                float b[8] = {b0.x, b0.y, b0.z, b0.w, b1.x, b1.y, b1.z, b1.w};
#pragma unroll
                for (int i = 0; i < TM; i++) {
#pragma unroll
                    for (int j = 0; j < 8; j++) acc[i][j] += a[i][t] * b[j];
                }
            }
        }
    }

    if (EPI <= 1) {
#pragma unroll
        for (int i = 0; i < TM; i++) {
            float4 v0, v1;
            v0.x = acc[i][0] + bias[ncOff + cA + 0];
            v0.y = acc[i][1] + bias[ncOff + cA + 1];
            v0.z = acc[i][2] + bias[ncOff + cA + 2];
            v0.w = acc[i][3] + bias[ncOff + cA + 3];
            v1.x = acc[i][4] + bias[ncOff + cB + 0];
            v1.y = acc[i][5] + bias[ncOff + cB + 1];
            v1.z = acc[i][6] + bias[ncOff + cB + 2];
            v1.w = acc[i][7] + bias[ncOff + cB + 3];
            if (EPI == 1) {
                v0.x = fmaxf(v0.x, 0.f); v0.y = fmaxf(v0.y, 0.f);
                v0.z = fmaxf(v0.z, 0.f); v0.w = fmaxf(v0.w, 0.f);
                v1.x = fmaxf(v1.x, 0.f); v1.y = fmaxf(v1.y, 0.f);
                v1.z = fmaxf(v1.z, 0.f); v1.w = fmaxf(v1.w, 0.f);
            }
            *(float4*)(outS + (m0 + i) * ldo + outOff + cA) = v0;
            *(float4*)(outS + (m0 + i) * ldo + outOff + cB) = v1;
        }
    } else {
        // final: relu(acc + bc) + o2, then inference batchnorm, write to global
#pragma unroll
        for (int i = 0; i < TM; i++) {
            const int vox = fp->voxBase + m0 + i;
            float* op = fp->out + (size_t)vox * 256;
            const float* o2r = fp->o2 + (m0 + i) * 256;
#pragma unroll
            for (int half = 0; half < 2; ++half) {
                const int cbase = half ? cB : cA;
                float res[4];
#pragma unroll
                for (int j = 0; j < 4; j++) {
                    int c = cbase + j;
                    float r = fmaxf(acc[i][half * 4 + j] + bias[c], 0.f);
                    float val = r + o2r[c];
                    res[j] = (val - fp->mu[c]) * rsqrtf(fp->var[c] + BN_EPS) * fp->gamma[c]
                             + fp->beta[c];
                }
                float4 vv = {res[0], res[1], res[2], res[3]};
                *(float4*)(op + cbase) = vv;
            }
        }
    }
}

// per-voxel attention among 16 heads; one warp handles 4 voxels.
// reads Q/KB/VB, writes attn_out over VB.
__device__ __forceinline__ void attention_phase(float* sm)
{
    const int tid  = threadIdx.x;
    const int w    = tid >> 5;
    const int lane = tid & 31;
    const int h    = lane >> 1;         // head 0..15 (lane pair)
    const int g0   = (lane & 1) * 8;    // this lane covers g in [g0, g0+8)
    const float scale = 0.17677669529663687f;  // 1/sqrt(32)

    for (int mv = 0; mv < 4; ++mv) {
        const int m = w * 4 + mv;
        const float* Qr = sm + Q_OFF + m * 512 + h * 32;
        const float* Kr = sm + KB_OFF + m * 512;
        float* Vr = sm + VB_OFF + m * 256;

        float4 q[8];
#pragma unroll
        for (int i = 0; i < 8; i++) q[i] = *(const float4*)(Qr + i * 4);

        float s[8];
#pragma unroll
        for (int gi = 0; gi < 8; ++gi) {
            const float* kp = Kr + (g0 + gi) * 32;
            float d = 0.f;
#pragma unroll
            for (int i = 0; i < 8; i++) {
                float4 kv = *(const float4*)(kp + i * 4);
                d += q[i].x * kv.x + q[i].y * kv.y + q[i].z * kv.z + q[i].w * kv.w;
            }
            s[gi] = d * scale;
        }

        // softmax over 16 g (combine lane pair via shfl xor 1)
        float mx = s[0];
#pragma unroll
        for (int gi = 1; gi < 8; ++gi) mx = fmaxf(mx, s[gi]);
        mx = fmaxf(mx, __shfl_xor_sync(0xffffffffu, mx, 1));
        float e[8], sum = 0.f;
#pragma unroll
        for (int gi = 0; gi < 8; ++gi) { e[gi] = expf(s[gi] - mx); sum += e[gi]; }
        sum += __shfl_xor_sync(0xffffffffu, sum, 1);
        const float inv = 1.f / sum;

        float o[16];
#pragma unroll
        for (int v = 0; v < 16; ++v) o[v] = 0.f;
#pragma unroll
        for (int gi = 0; gi < 8; ++gi) {
            const float p = e[gi] * inv;
            const float* vp = Vr + (g0 + gi) * 16;
#pragma unroll
            for (int v4 = 0; v4 < 4; ++v4) {
                float4 vv = *(const float4*)(vp + v4 * 4);
                o[v4 * 4 + 0] += p * vv.x;
                o[v4 * 4 + 1] += p * vv.y;
                o[v4 * 4 + 2] += p * vv.z;
                o[v4 * 4 + 3] += p * vv.w;
            }
        }
#pragma unroll
        for (int v = 0; v < 16; ++v) o[v] += __shfl_xor_sync(0xffffffffu, o[v], 1);

        __syncwarp();  // all V reads for this warp's voxel done before overwrite
        const int vbase = (lane & 1) * 8;
        float* ao = Vr + h * 16 + vbase;
        float4 w0 = {o[vbase + 0], o[vbase + 1], o[vbase + 2], o[vbase + 3]};
        float4 w1 = {o[vbase + 4], o[vbase + 5], o[vbase + 6], o[vbase + 7]};
        *(float4*)(ao) = w0;
        *(float4*)(ao + 4) = w1;
        __syncwarp();
    }
}

__global__ void __launch_bounds__(THREADS, 1) msa_fused_kernel(
    const float* __restrict__ x,
    const float* __restrict__ Wq, const float* __restrict__ bq,
    const float* __restrict__ Wk, const float* __restrict__ bk,
    const float* __restrict__ Wv, const float* __restrict__ bv,
    const float* __restrict__ W1, const float* __restrict__ b1,
    const float* __restrict__ Wo, const float* __restrict__ bo,
    const float* __restrict__ Wc, const float* __restrict__ bc,
    const float* __restrict__ gamma, const float* __restrict__ beta,
    const float* __restrict__ mu, const float* __restrict__ var,
    float* __restrict__ out)
{
    extern __shared__ float sm[];
    const int tid = threadIdx.x;
    const int voxBase = blockIdx.x * TILE_M;

    // load X tile [32][256]
    {
        const float4* src = (const float4*)(x + (size_t)voxBase * 256);
        float4* dst = (float4*)(sm + XS_OFF);
#pragma unroll
        for (int i = 0; i < 8; i++) dst[tid + i * THREADS] = src[tid + i * THREADS];
    }
    // (visibility of Xs guaranteed by the leading __syncthreads inside the first gemm)

    // Q = x @ Wq + bq  ;  K = x @ Wk + bk  ;  V = x @ Wv + bv
    gemm_tile<512, 0>(sm + XS_OFF, 256, 256, Wq, 512, 0, bq, sm + Q_OFF, 512, 0, sm + BS_OFF, nullptr);
    gemm_tile<512, 0>(sm + XS_OFF, 256, 256, Wk, 512, 0, bk, sm + KB_OFF, 512, 0, sm + BS_OFF, nullptr);
    gemm_tile<256, 0>(sm + XS_OFF, 256, 256, Wv, 256, 0, bv, sm + VB_OFF, 256, 0, sm + BS_OFF, nullptr);
    __syncthreads();

    attention_phase(sm);          // VB now holds attn_out [32][256]
    __syncthreads();

    // inter = relu(attn_out @ W1 + b1)   [32][1024] into INTER (overlaps Q+KB)
    gemm_tile<512, 1>(sm + VB_OFF, 256, 256, W1, 1024, 0,   b1, sm + INTER_OFF, 1024, 0,   sm + BS_OFF, nullptr);
    gemm_tile<512, 1>(sm + VB_OFF, 256, 256, W1, 1024, 512, b1, sm + INTER_OFF, 1024, 512, sm + BS_OFF, nullptr);
    __syncthreads();

    // o2 = inter @ Wo + bo  -> VB (attn_out dead)
    gemm_tile<256, 0>(sm + INTER_OFF, 1024, 1024, Wo, 256, 0, bo, sm + VB_OFF, 256, 0, sm + BS_OFF, nullptr);
    __syncthreads();

    // y = (relu(x @ Wc + bc) + o2 - mu) * rsqrt(var+eps) * gamma + beta
    FinalP fp;
    fp.gamma = gamma; fp.beta = beta; fp.mu = mu; fp.var = var;
    fp.o2 = sm + VB_OFF; fp.out = out; fp.voxBase = voxBase;
    gemm_tile<256, 2>(sm + XS_OFF, 256, 256, Wc, 256, 0, bc, nullptr, 0, 0, sm + BS_OFF, &fp);
}

extern "C" void kernel_launch(void* const* d_in, const int* in_sizes, int n_in,
                              void* d_out, int out_size)
{
    const float* x     = (const float*)d_in[0];
    const float* Wq    = (const float*)d_in[1];
    const float* bq    = (const float*)d_in[2];
    const float* Wk    = (const float*)d_in[3];
    const float* bk    = (const float*)d_in[4];
    const float* Wv    = (const float*)d_in[5];
    const float* bv    = (const float*)d_in[6];
    const float* W1    = (const float*)d_in[7];
    const float* b1    = (const float*)d_in[8];
    const float* Wo    = (const float*)d_in[9];
    const float* bo    = (const float*)d_in[10];
    const float* Wc    = (const float*)d_in[11];
    const float* bc    = (const float*)d_in[12];
    const float* gamma = (const float*)d_in[13];
    const float* beta  = (const float*)d_in[14];
    const float* mu    = (const float*)d_in[15];
    const float* var   = (const float*)d_in[16];
    float* out = (float*)d_out;

    const int nvox = in_sizes[0] / 256;         // 131072
    const int grid = nvox / TILE_M;             // 4096

    cudaFuncSetAttribute(msa_fused_kernel,
                         cudaFuncAttributeMaxDynamicSharedMemorySize, SMEM_BYTES);
    msa_fused_kernel<<<grid, THREADS, SMEM_BYTES>>>(
        x, Wq, bq, Wk, bk, Wv, bv, W1, b1, Wo, bo, Wc, bc,
        gamma, beta, mu, var, out);
}

// round 5
// speedup vs baseline: 1.0007x; 1.0007x over previous
#include <cuda_runtime.h>

// MSAAttentionBlock fused kernel (fp32 baseline).
// Per 32-voxel tile: X(smem) -> Q,K,V -> per-voxel head attention -> FFN -> residual+BN -> out.
// All intermediates live in shared memory; weights staged through a shared k-tile buffer.

#define THREADS 256
#define TILE_M  32
#define BK      16
#define BN_EPS  1e-6f

// shared memory layout (float offsets)
#define XS_OFF     0        // [32][256]  32KB  (resident: x tile)
#define Q_OFF      8192     // [32][512]  64KB
#define KB_OFF     24576    // [32][512]  64KB
#define VB_OFF     40960    // [32][256]  32KB  (v, then attn_out, then o2)
#define BS_OFF     49152    // [16][512]  32KB  (weight k-tile)
#define INTER_OFF  8192     // [32][1024] 128KB (overlaps Q+KB, used after attention)
#define SMEM_FLOATS 57344
#define SMEM_BYTES  (SMEM_FLOATS * 4)   // 229376 B <= 232448 B (227KB) sm_103a limit

struct FinalP {
    const float* gamma;
    const float* beta;
    const float* mu;
    const float* var;
    const float* o2;     // smem o2 [32][256]
    float*       out;    // global output
    int          voxBase;
};

// C[32][NC] (+ncOff) = A[32][K] @ W[K][ldw] slice, bias add, optional relu / final epilogue.
// EPI: 0 = store to smem, 1 = store+relu to smem, 2 = final (relu + o2 + batchnorm -> global)
template <int NC, int EPI>
__device__ __forceinline__ void gemm_tile(
    const float* A, int lda, int K,
    const float* __restrict__ W, int ldw, int ncOff,
    const float* __restrict__ bias,
    float* outS, int ldo, int outOff,
    float* Bs, const FinalP* fp)
{
    constexpr int NB = NC / 8;        // n-blocks (threads along n)
    constexpr int MG = THREADS / NB;  // m-groups
    constexpr int TM = TILE_M / MG;   // rows per thread
    const int tid  = threadIdx.x;
    const int nIdx = tid % NB;
    const int mIdx = tid / NB;
    const int m0   = mIdx * TM;
    const int cA   = nIdx * 4;        // split-column layout: conflict-free LDS.128
    const int cB   = cA + NC / 2;

    float acc[TM][8];
#pragma unroll
    for (int i = 0; i < TM; i++)
#pragma unroll
        for (int j = 0; j < 8; j++) acc[i][j] = 0.f;

    const int KT = K / BK;
    for (int kt = 0; kt < KT; ++kt) {
        __syncthreads();   // protect Bs (prev consumers done) + previous phase outputs
        {
            constexpr int ELEMS = BK * NC;
            const float* Wrow = W + (size_t)kt * BK * ldw + ncOff;
#pragma unroll
            for (int base = 0; base < ELEMS; base += THREADS * 4) {
                int idx = base + tid * 4;
                int r = idx / NC;
                int c = idx - r * NC;
                float4 v = *(const float4*)(Wrow + (size_t)r * ldw + c);
                *(float4*)(Bs + idx) = v;
            }
        }
        __syncthreads();

        const float* Ak = A + kt * BK;
#pragma unroll
        for (int kk4 = 0; kk4 < BK / 4; ++kk4) {
            float a[TM][4];
#pragma unroll
            for (int i = 0; i < TM; i++) {
                float4 t4 = *(const float4*)(Ak + (m0 + i) * lda + kk4 * 4);
                a[i][0] = t4.x; a[i][1] = t4.y; a[i][2] = t4.z; a[i][3] = t4.w;
            }
#pragma unroll
            for (int t = 0; t < 4; t++) {
                const float* Br = Bs + (kk4 * 4 + t) * NC;
                float4 b0 = *(const float4*)(Br + cA);
                float4 b1 = *(const float4*)(Br + cB);
                float b[8] = {b0.x, b0.y, b0.z, b0.w, b1.x, b1.y, b1.z, b1.w};
#pragma unroll
                for (int i = 0; i < TM; i++) {
#pragma unroll
                    for (int j = 0; j < 8; j++) acc[i][j] += a[i][t] * b[j];
                }
            }
        }
    }

    if (EPI <= 1) {
#pragma unroll
        for (int i = 0; i < TM; i++) {
            float4 v0, v1;
            v0.x = acc[i][0] + bias[ncOff + cA + 0];
            v0.y = acc[i][1] + bias[ncOff + cA + 1];
            v0.z = acc[i][2] + bias[ncOff + cA + 2];
            v0.w = acc[i][3] + bias[ncOff + cA + 3];
            v1.x = acc[i][4] + bias[ncOff + cB + 0];
            v1.y = acc[i][5] + bias[ncOff + cB + 1];
            v1.z = acc[i][6] + bias[ncOff + cB + 2];
            v1.w = acc[i][7] + bias[ncOff + cB + 3];
            if (EPI == 1) {
                v0.x = fmaxf(v0.x, 0.f); v0.y = fmaxf(v0.y, 0.f);
                v0.z = fmaxf(v0.z, 0.f); v0.w = fmaxf(v0.w, 0.f);
                v1.x = fmaxf(v1.x, 0.f); v1.y = fmaxf(v1.y, 0.f);
                v1.z = fmaxf(v1.z, 0.f); v1.w = fmaxf(v1.w, 0.f);
            }
            *(float4*)(outS + (m0 + i) * ldo + outOff + cA) = v0;
            *(float4*)(outS + (m0 + i) * ldo + outOff + cB) = v1;
        }
    } else {
        // final: relu(acc + bc) + o2, then inference batchnorm, write to global
#pragma unroll
        for (int i = 0; i < TM; i++) {
            const int vox = fp->voxBase + m0 + i;
            float* op = fp->out + (size_t)vox * 256;
            const float* o2r = fp->o2 + (m0 + i) * 256;
#pragma unroll
            for (int half = 0; half < 2; ++half) {
                const int cbase = half ? cB : cA;
                float res[4];
#pragma unroll
                for (int j = 0; j < 4; j++) {
                    int c = cbase + j;
                    float r = fmaxf(acc[i][half * 4 + j] + bias[c], 0.f);
                    float val = r + o2r[c];
                    res[j] = (val - fp->mu[c]) * rsqrtf(fp->var[c] + BN_EPS) * fp->gamma[c]
                             + fp->beta[c];
                }
                float4 vv = {res[0], res[1], res[2], res[3]};
                *(float4*)(op + cbase) = vv;
            }
        }
    }
}

// per-voxel attention among 16 heads; one warp handles 4 voxels.
// reads Q/KB/VB, writes attn_out over VB.
__device__ __forceinline__ void attention_phase(float* sm)
{
    const int tid  = threadIdx.x;
    const int w    = tid >> 5;
    const int lane = tid & 31;
    const int h    = lane >> 1;         // head 0..15 (lane pair)
    const int g0   = (lane & 1) * 8;    // this lane covers g in [g0, g0+8)
    const float scale = 0.17677669529663687f;  // 1/sqrt(32)

    for (int mv = 0; mv < 4; ++mv) {
        const int m = w * 4 + mv;
        const float* Qr = sm + Q_OFF + m * 512 + h * 32;
        const float* Kr = sm + KB_OFF + m * 512;
        float* Vr = sm + VB_OFF + m * 256;

        float4 q[8];
#pragma unroll
        for (int i = 0; i < 8; i++) q[i] = *(const float4*)(Qr + i * 4);

        float s[8];
#pragma unroll
        for (int gi = 0; gi < 8; ++gi) {
            const float* kp = Kr + (g0 + gi) * 32;
            float d = 0.f;
#pragma unroll
            for (int i = 0; i < 8; i++) {
                float4 kv = *(const float4*)(kp + i * 4);
                d += q[i].x * kv.x + q[i].y * kv.y + q[i].z * kv.z + q[i].w * kv.w;
            }
            s[gi] = d * scale;
        }

        // softmax over 16 g (combine lane pair via shfl xor 1)
        float mx = s[0];
#pragma unroll
        for (int gi = 1; gi < 8; ++gi) mx = fmaxf(mx, s[gi]);
        mx = fmaxf(mx, __shfl_xor_sync(0xffffffffu, mx, 1));
        float e[8], sum = 0.f;
#pragma unroll
        for (int gi = 0; gi < 8; ++gi) { e[gi] = expf(s[gi] - mx); sum += e[gi]; }
        sum += __shfl_xor_sync(0xffffffffu, sum, 1);
        const float inv = 1.f / sum;

        float o[16];
#pragma unroll
        for (int v = 0; v < 16; ++v) o[v] = 0.f;
#pragma unroll
        for (int gi = 0; gi < 8; ++gi) {
            const float p = e[gi] * inv;
            const float* vp = Vr + (g0 + gi) * 16;
#pragma unroll
            for (int v4 = 0; v4 < 4; ++v4) {
                float4 vv = *(const float4*)(vp + v4 * 4);
                o[v4 * 4 + 0] += p * vv.x;
                o[v4 * 4 + 1] += p * vv.y;
                o[v4 * 4 + 2] += p * vv.z;
                o[v4 * 4 + 3] += p * vv.w;
            }
        }
#pragma unroll
        for (int v = 0; v < 16; ++v) o[v] += __shfl_xor_sync(0xffffffffu, o[v], 1);

        __syncwarp();  // all V reads for this warp's voxel done before overwrite
        const int vbase = (lane & 1) * 8;
        float* ao = Vr + h * 16 + vbase;
        float4 w0 = {o[vbase + 0], o[vbase + 1], o[vbase + 2], o[vbase + 3]};
        float4 w1 = {o[vbase + 4], o[vbase + 5], o[vbase + 6], o[vbase + 7]};
        *(float4*)(ao) = w0;
        *(float4*)(ao + 4) = w1;
        __syncwarp();
    }
}

__global__ void __launch_bounds__(THREADS, 1) msa_fused_kernel(
    const float* __restrict__ x,
    const float* __restrict__ Wq, const float* __restrict__ bq,
    const float* __restrict__ Wk, const float* __restrict__ bk,
    const float* __restrict__ Wv, const float* __restrict__ bv,
    const float* __restrict__ W1, const float* __restrict__ b1,
    const float* __restrict__ Wo, const float* __restrict__ bo,
    const float* __restrict__ Wc, const float* __restrict__ bc,
    const float* __restrict__ gamma, const float* __restrict__ beta,
    const float* __restrict__ mu, const float* __restrict__ var,
    float* __restrict__ out)
{
    extern __shared__ float sm[];
    const int tid = threadIdx.x;
    const int voxBase = blockIdx.x * TILE_M;

    // load X tile [32][256]
    {
        const float4* src = (const float4*)(x + (size_t)voxBase * 256);
        float4* dst = (float4*)(sm + XS_OFF);
#pragma unroll
        for (int i = 0; i < 8; i++) dst[tid + i * THREADS] = src[tid + i * THREADS];
    }
    // (visibility of Xs guaranteed by the leading __syncthreads inside the first gemm)

    // Q = x @ Wq + bq  ;  K = x @ Wk + bk  ;  V = x @ Wv + bv
    gemm_tile<512, 0>(sm + XS_OFF, 256, 256, Wq, 512, 0, bq, sm + Q_OFF, 512, 0, sm + BS_OFF, nullptr);
    gemm_tile<512, 0>(sm + XS_OFF, 256, 256, Wk, 512, 0, bk, sm + KB_OFF, 512, 0, sm + BS_OFF, nullptr);
    gemm_tile<256, 0>(sm + XS_OFF, 256, 256, Wv, 256, 0, bv, sm + VB_OFF, 256, 0, sm + BS_OFF, nullptr);
    __syncthreads();

    attention_phase(sm);          // VB now holds attn_out [32][256]
    __syncthreads();

    // inter = relu(attn_out @ W1 + b1)   [32][1024] into INTER (overlaps Q+KB)
    gemm_tile<512, 1>(sm + VB_OFF, 256, 256, W1, 1024, 0,   b1, sm + INTER_OFF, 1024, 0,   sm + BS_OFF, nullptr);
    gemm_tile<512, 1>(sm + VB_OFF, 256, 256, W1, 1024, 512, b1, sm + INTER_OFF, 1024, 512, sm + BS_OFF, nullptr);
    __syncthreads();

    // o2 = inter @ Wo + bo  -> VB (attn_out dead)
    gemm_tile<256, 0>(sm + INTER_OFF, 1024, 1024, Wo, 256, 0, bo, sm + VB_OFF, 256, 0, sm + BS_OFF, nullptr);
    __syncthreads();

    // y = (relu(x @ Wc + bc) + o2 - mu) * rsqrt(var+eps) * gamma + beta
    FinalP fp;
    fp.gamma = gamma; fp.beta = beta; fp.mu = mu; fp.var = var;
    fp.o2 = sm + VB_OFF; fp.out = out; fp.voxBase = voxBase;
    gemm_tile<256, 2>(sm + XS_OFF, 256, 256, Wc, 256, 0, bc, nullptr, 0, 0, sm + BS_OFF, &fp);
}

extern "C" void kernel_launch(void* const* d_in, const int* in_sizes, int n_in,
                              void* d_out, int out_size)
{
    const float* x     = (const float*)d_in[0];
    const float* Wq    = (const float*)d_in[1];
    const float* bq    = (const float*)d_in[2];
    const float* Wk    = (const float*)d_in[3];
    const float* bk    = (const float*)d_in[4];
    const float* Wv    = (const float*)d_in[5];
    const float* bv    = (const float*)d_in[6];
    const float* W1    = (const float*)d_in[7];
    const float* b1    = (const float*)d_in[8];
    const float* Wo    = (const float*)d_in[9];
    const float* bo    = (const float*)d_in[10];
    const float* Wc    = (const float*)d_in[11];
    const float* bc    = (const float*)d_in[12];
    const float* gamma = (const float*)d_in[13];
    const float* beta  = (const float*)d_in[14];
    const float* mu    = (const float*)d_in[15];
    const float* var   = (const float*)d_in[16];
    float* out = (float*)d_out;

    const int nvox = in_sizes[0] / 256;         // 131072
    const int grid = nvox / TILE_M;             // 4096

    cudaFuncSetAttribute(msa_fused_kernel,
                         cudaFuncAttributeMaxDynamicSharedMemorySize, SMEM_BYTES);
    msa_fused_kernel<<<grid, THREADS, SMEM_BYTES>>>(
        x, Wq, bq, Wk, bk, Wv, bv, W1, b1, Wo, bo, Wc, bc,
        gamma, beta, mu, var, out);
}

// round 7
// speedup vs baseline: 1.2474x; 1.2466x over previous
#include <cuda_runtime.h>

// MSAAttentionBlock fused kernel (fp32, FFMA2 f32x2 packed math + weight reg-prefetch).
// Per 32-voxel tile: X(smem) -> Q,K,V -> per-voxel head attention -> FFN -> residual+BN -> out.
// All intermediates live in shared memory; weights staged through a shared k-tile buffer,
// double-buffered through registers so LDG latency overlaps compute.

#define THREADS 256
#define TILE_M  32
#define BK      16
#define BN_EPS  1e-6f

// shared memory layout (float offsets)
#define XS_OFF     0        // [32][256]  32KB  (resident: x tile)
#define Q_OFF      8192     // [32][512]  64KB
#define KB_OFF     24576    // [32][512]  64KB
#define VB_OFF     40960    // [32][256]  32KB  (v, then attn_out, then o2)
#define BS_OFF     49152    // [16][512]  32KB  (weight k-tile)
#define INTER_OFF  8192     // [32][1024] 128KB (overlaps Q+KB, used after attention)
#define SMEM_FLOATS 57344
#define SMEM_BYTES  (SMEM_FLOATS * 4)   // 229376 B <= 232448 B sm_103a limit

// packed fp32x2 FMA (Blackwell-only; doubles fp32 MAC rate vs 3-reg FFMA)
#define FMA2(d, a, b) asm("fma.rn.f32x2 %0, %1, %2, %0;" : "+l"(d) : "l"(a), "l"(b))
#define PACK2(d, s)   asm("mov.b64 %0, {%1, %1};" : "=l"(d) : "f"(s))

struct FinalP {
    const float* gamma;
    const float* beta;
    const float* mu;
    const float* var;
    const float* o2;     // smem o2 [32][256]
    float*       out;    // global output
    int          voxBase;
};

// C[32][NC] (+ncOff) = A[32][K] @ W[K][ldw] slice, bias add, optional relu / final epilogue.
// EPI: 0 = store to smem, 1 = store+relu to smem, 2 = final (relu + o2 + batchnorm -> global)
template <int NC, int EPI>
__device__ __forceinline__ void gemm_tile(
    const float* A, int lda, int K,
    const float* __restrict__ W, int ldw, int ncOff,
    const float* __restrict__ bias,
    float* outS, int ldo, int outOff,
    float* Bs, const FinalP* fp)
{
    constexpr int NB  = NC / 8;        // n-blocks (threads along n)
    constexpr int MG  = THREADS / NB;  // m-groups
    constexpr int TM  = TILE_M / MG;   // rows per thread
    constexpr int NLD = (BK * NC) / (THREADS * 4);  // weight float4 loads / thread / ktile
    const int tid  = threadIdx.x;
    const int nIdx = tid % NB;
    const int mIdx = tid / NB;
    const int m0   = mIdx * TM;
    const int cA   = nIdx * 4;        // split-column layout: conflict-free LDS.128
    const int cB   = cA + NC / 2;

    // accumulators: col pairs (cA,cA+1),(cA+2,cA+3),(cB,cB+1),(cB+2,cB+3)
    unsigned long long acc2[TM][4];
#pragma unroll
    for (int i = 0; i < TM; i++)
#pragma unroll
        for (int j = 0; j < 4; j++) acc2[i][j] = 0ull;

    const int KT = K / BK;

    // prologue: prefetch ktile 0 into registers
    float4 wreg[NLD];
#pragma unroll
    for (int l = 0; l < NLD; l++) {
        int idx = l * THREADS * 4 + tid * 4;
        int r = idx / NC;
        int c = idx - r * NC;
        wreg[l] = *(const float4*)(W + (size_t)r * ldw + ncOff + c);
    }

    for (int kt = 0; kt < KT; ++kt) {
        __syncthreads();   // prev consumers of Bs done + previous phase outputs visible
#pragma unroll
        for (int l = 0; l < NLD; l++) {
            int idx = l * THREADS * 4 + tid * 4;
            *(float4*)(Bs + idx) = wreg[l];
        }
        __syncthreads();

        // prefetch next ktile (LDG latency overlaps the FMA loop below)
        if (kt + 1 < KT) {
            const float* Wn = W + (size_t)(kt + 1) * BK * ldw + ncOff;
#pragma unroll
            for (int l = 0; l < NLD; l++) {
                int idx = l * THREADS * 4 + tid * 4;
                int r = idx / NC;
                int c = idx - r * NC;
                wreg[l] = *(const float4*)(Wn + (size_t)r * ldw + c);
            }
        }

        const float* Ak = A + kt * BK;
#pragma unroll
        for (int kk4 = 0; kk4 < BK / 4; ++kk4) {
            float a[TM][4];
#pragma unroll
            for (int i = 0; i < TM; i++) {
                float4 t4 = *(const float4*)(Ak + (m0 + i) * lda + kk4 * 4);
                a[i][0] = t4.x; a[i][1] = t4.y; a[i][2] = t4.z; a[i][3] = t4.w;
            }
#pragma unroll
            for (int t = 0; t < 4; t++) {
                const float* Br = Bs + (kk4 * 4 + t) * NC;
                ulonglong2 bA = *(const ulonglong2*)(Br + cA);   // cols cA..cA+3
                ulonglong2 bB = *(const ulonglong2*)(Br + cB);   // cols cB..cB+3
#pragma unroll
                for (int i = 0; i < TM; i++) {
                    unsigned long long aa;
                    PACK2(aa, a[i][t]);
                    FMA2(acc2[i][0], aa, bA.x);
                    FMA2(acc2[i][1], aa, bA.y);
                    FMA2(acc2[i][2], aa, bB.x);
                    FMA2(acc2[i][3], aa, bB.y);
                }
            }
        }
    }

    if (EPI <= 1) {
#pragma unroll
        for (int i = 0; i < TM; i++) {
            float2 p0 = *reinterpret_cast<float2*>(&acc2[i][0]);
            float2 p1 = *reinterpret_cast<float2*>(&acc2[i][1]);
            float2 p2 = *reinterpret_cast<float2*>(&acc2[i][2]);
            float2 p3 = *reinterpret_cast<float2*>(&acc2[i][3]);
            float4 v0, v1;
            v0.x = p0.x + bias[ncOff + cA + 0];
            v0.y = p0.y + bias[ncOff + cA + 1];
            v0.z = p1.x + bias[ncOff + cA + 2];
            v0.w = p1.y + bias[ncOff + cA + 3];
            v1.x = p2.x + bias[ncOff + cB + 0];
            v1.y = p2.y + bias[ncOff + cB + 1];
            v1.z = p3.x + bias[ncOff + cB + 2];
            v1.w = p3.y + bias[ncOff + cB + 3];
            if (EPI == 1) {
                v0.x = fmaxf(v0.x, 0.f); v0.y = fmaxf(v0.y, 0.f);
                v0.z = fmaxf(v0.z, 0.f); v0.w = fmaxf(v0.w, 0.f);
                v1.x = fmaxf(v1.x, 0.f); v1.y = fmaxf(v1.y, 0.f);
                v1.z = fmaxf(v1.z, 0.f); v1.w = fmaxf(v1.w, 0.f);
            }
            *(float4*)(outS + (m0 + i) * ldo + outOff + cA) = v0;
            *(float4*)(outS + (m0 + i) * ldo + outOff + cB) = v1;
        }
    } else {
        // final: relu(acc + bc) + o2, then inference batchnorm, write to global
#pragma unroll
        for (int i = 0; i < TM; i++) {
            const int vox = fp->voxBase + m0 + i;
            float* op = fp->out + (size_t)vox * 256;
            const float* o2r = fp->o2 + (m0 + i) * 256;
            float accf[8];
#pragma unroll
            for (int j = 0; j < 4; j++) {
                float2 p = *reinterpret_cast<float2*>(&acc2[i][j]);
                accf[j * 2 + 0] = p.x;
                accf[j * 2 + 1] = p.y;
            }
#pragma unroll
            for (int half = 0; half < 2; ++half) {
                const int cbase = half ? cB : cA;
                float res[4];
#pragma unroll
                for (int j = 0; j < 4; j++) {
                    int c = cbase + j;
                    float r = fmaxf(accf[half * 4 + j] + bias[c], 0.f);
                    float val = r + o2r[c];
                    res[j] = (val - fp->mu[c]) * rsqrtf(fp->var[c] + BN_EPS) * fp->gamma[c]
                             + fp->beta[c];
                }
                float4 vv = {res[0], res[1], res[2], res[3]};
                *(float4*)(op + cbase) = vv;
            }
        }
    }
}

// per-voxel attention among 16 heads; one warp handles 4 voxels.
// reads Q/KB/VB, writes attn_out over VB.
__device__ __forceinline__ void attention_phase(float* sm)
{
    const int tid  = threadIdx.x;
    const int w    = tid >> 5;
    const int lane = tid & 31;
    const int h    = lane >> 1;         // head 0..15 (lane pair)
    const int g0   = (lane & 1) * 8;    // this lane covers g in [g0, g0+8)
    const float scale = 0.17677669529663687f;  // 1/sqrt(32)

    for (int mv = 0; mv < 4; ++mv) {
        const int m = w * 4 + mv;
        const float* Qr = sm + Q_OFF + m * 512 + h * 32;
        const float* Kr = sm + KB_OFF + m * 512;
        float* Vr = sm + VB_OFF + m * 256;

        float4 q[8];
#pragma unroll
        for (int i = 0; i < 8; i++) q[i] = *(const float4*)(Qr + i * 4);

        float s[8];
#pragma unroll
        for (int gi = 0; gi < 8; ++gi) {
            const float* kp = Kr + (g0 + gi) * 32;
            float d = 0.f;
#pragma unroll
            for (int i = 0; i < 8; i++) {
                float4 kv = *(const float4*)(kp + i * 4);
                d += q[i].x * kv.x + q[i].y * kv.y + q[i].z * kv.z + q[i].w * kv.w;
            }
            s[gi] = d * scale;
        }

        // softmax over 16 g (combine lane pair via shfl xor 1)
        float mx = s[0];
#pragma unroll
        for (int gi = 1; gi < 8; ++gi) mx = fmaxf(mx, s[gi]);
        mx = fmaxf(mx, __shfl_xor_sync(0xffffffffu, mx, 1));
        float e[8], sum = 0.f;
#pragma unroll
        for (int gi = 0; gi < 8; ++gi) { e[gi] = expf(s[gi] - mx); sum += e[gi]; }
        sum += __shfl_xor_sync(0xffffffffu, sum, 1);
        const float inv = 1.f / sum;

        float o[16];
#pragma unroll
        for (int v = 0; v < 16; ++v) o[v] = 0.f;
#pragma unroll
        for (int gi = 0; gi < 8; ++gi) {
            const float p = e[gi] * inv;
            const float* vp = Vr + (g0 + gi) * 16;
#pragma unroll
            for (int v4 = 0; v4 < 4; ++v4) {
                float4 vv = *(const float4*)(vp + v4 * 4);
                o[v4 * 4 + 0] += p * vv.x;
                o[v4 * 4 + 1] += p * vv.y;
                o[v4 * 4 + 2] += p * vv.z;
                o[v4 * 4 + 3] += p * vv.w;
            }
        }
#pragma unroll
        for (int v = 0; v < 16; ++v) o[v] += __shfl_xor_sync(0xffffffffu, o[v], 1);

        __syncwarp();  // all V reads for this warp's voxel done before overwrite
        const int vbase = (lane & 1) * 8;
        float* ao = Vr + h * 16 + vbase;
        float4 w0 = {o[vbase + 0], o[vbase + 1], o[vbase + 2], o[vbase + 3]};
        float4 w1 = {o[vbase + 4], o[vbase + 5], o[vbase + 6], o[vbase + 7]};
        *(float4*)(ao) = w0;
        *(float4*)(ao + 4) = w1;
        __syncwarp();
    }
}

__global__ void __launch_bounds__(THREADS, 1) msa_fused_kernel(
    const float* __restrict__ x,
    const float* __restrict__ Wq, const float* __restrict__ bq,
    const float* __restrict__ Wk, const float* __restrict__ bk,
    const float* __restrict__ Wv, const float* __restrict__ bv,
    const float* __restrict__ W1, const float* __restrict__ b1,
    const float* __restrict__ Wo, const float* __restrict__ bo,
    const float* __restrict__ Wc, const float* __restrict__ bc,
    const float* __restrict__ gamma, const float* __restrict__ beta,
    const float* __restrict__ mu, const float* __restrict__ var,
    float* __restrict__ out)
{
    extern __shared__ float sm[];
    const int tid = threadIdx.x;
    const int voxBase = blockIdx.x * TILE_M;

    // load X tile [32][256]
    {
        const float4* src = (const float4*)(x + (size_t)voxBase * 256);
        float4* dst = (float4*)(sm + XS_OFF);
#pragma unroll
        for (int i = 0; i < 8; i++) dst[tid + i * THREADS] = src[tid + i * THREADS];
    }
    // (visibility of Xs guaranteed by the leading __syncthreads inside the first gemm)

    // Q = x @ Wq + bq  ;  K = x @ Wk + bk  ;  V = x @ Wv + bv
    gemm_tile<512, 0>(sm + XS_OFF, 256, 256, Wq, 512, 0, bq, sm + Q_OFF, 512, 0, sm + BS_OFF, nullptr);
    gemm_tile<512, 0>(sm + XS_OFF, 256, 256, Wk, 512, 0, bk, sm + KB_OFF, 512, 0, sm + BS_OFF, nullptr);
    gemm_tile<256, 0>(sm + XS_OFF, 256, 256, Wv, 256, 0, bv, sm + VB_OFF, 256, 0, sm + BS_OFF, nullptr);
    __syncthreads();

    attention_phase(sm);          // VB now holds attn_out [32][256]
    __syncthreads();

    // inter = relu(attn_out @ W1 + b1)   [32][1024] into INTER (overlaps Q+KB)
    gemm_tile<512, 1>(sm + VB_OFF, 256, 256, W1, 1024, 0,   b1, sm + INTER_OFF, 1024, 0,   sm + BS_OFF, nullptr);
    gemm_tile<512, 1>(sm + VB_OFF, 256, 256, W1, 1024, 512, b1, sm + INTER_OFF, 1024, 512, sm + BS_OFF, nullptr);
    __syncthreads();

    // o2 = inter @ Wo + bo  -> VB (attn_out dead)
    gemm_tile<256, 0>(sm + INTER_OFF, 1024, 1024, Wo, 256, 0, bo, sm + VB_OFF, 256, 0, sm + BS_OFF, nullptr);
    __syncthreads();

    // y = (relu(x @ Wc + bc) + o2 - mu) * rsqrt(var+eps) * gamma + beta
    FinalP fp;
    fp.gamma = gamma; fp.beta = beta; fp.mu = mu; fp.var = var;
    fp.o2 = sm + VB_OFF; fp.out = out; fp.voxBase = voxBase;
    gemm_tile<256, 2>(sm + XS_OFF, 256, 256, Wc, 256, 0, bc, nullptr, 0, 0, sm + BS_OFF, &fp);
}

extern "C" void kernel_launch(void* const* d_in, const int* in_sizes, int n_in,
                              void* d_out, int out_size)
{
    const float* x     = (const float*)d_in[0];
    const float* Wq    = (const float*)d_in[1];
    const float* bq    = (const float*)d_in[2];
    const float* Wk    = (const float*)d_in[3];
    const float* bk    = (const float*)d_in[4];
    const float* Wv    = (const float*)d_in[5];
    const float* bv    = (const float*)d_in[6];
    const float* W1    = (const float*)d_in[7];
    const float* b1    = (const float*)d_in[8];
    const float* Wo    = (const float*)d_in[9];
    const float* bo    = (const float*)d_in[10];
    const float* Wc    = (const float*)d_in[11];
    const float* bc    = (const float*)d_in[12];
    const float* gamma = (const float*)d_in[13];
    const float* beta  = (const float*)d_in[14];
    const float* mu    = (const float*)d_in[15];
    const float* var   = (const float*)d_in[16];
    float* out = (float*)d_out;

    const int nvox = in_sizes[0] / 256;         // 131072
    const int grid = nvox / TILE_M;             // 4096

    cudaFuncSetAttribute(msa_fused_kernel,
                         cudaFuncAttributeMaxDynamicSharedMemorySize, SMEM_BYTES);
    msa_fused_kernel<<<grid, THREADS, SMEM_BYTES>>>(
        x, Wq, bq, Wk, bk, Wv, bv, W1, b1, Wo, bo, Wc, bc,
        gamma, beta, mu, var, out);
}